// round 1
// baseline (speedup 1.0000x reference)
#include <cuda_runtime.h>
#include <math.h>

// Problem constants
#define NTOK 2048
#define HD   2048
#define NE   8
#define ID   1024
#define MAXPE 2048   // worst case: all tokens pick this expert

// Tiling
#define BM 128
#define BK 16

// Scratch (static device memory; no runtime allocation)
__device__ int   g_count[NE];
__device__ int   g_tok[NE * MAXPE];
__device__ float g_wt [NE * MAXPE];
__device__ float g_act[(size_t)NE * MAXPE * ID];   // 64 MB activation scratch

// ---------------------------------------------------------------------------
// init: zero expert counters and the output buffer (poisoned by harness)
// ---------------------------------------------------------------------------
__global__ void init_kernel(float4* __restrict__ out4) {
    int idx = blockIdx.x * blockDim.x + threadIdx.x;
    if (idx < NE) g_count[idx] = 0;
    if (idx < NTOK * HD / 4) out4[idx] = make_float4(0.f, 0.f, 0.f, 0.f);
}

// ---------------------------------------------------------------------------
// router: logits -> top-2 -> renormalized weights -> per-expert gather lists
// topk(softmax) == topk(logits); renorm(top2 of softmax) == softmax over the
// top-2 logits, so compute it directly.
// ---------------------------------------------------------------------------
__global__ void router_kernel(const float* __restrict__ x,
                              const float* __restrict__ gw) {
    int t = blockIdx.x;
    int tid = threadIdx.x;
    float p[NE];
#pragma unroll
    for (int e = 0; e < NE; e++) p[e] = 0.f;
    const float* xr = x + (size_t)t * HD;
    for (int h = tid; h < HD; h += 256) {
        float xv = xr[h];
        const float* g = gw + (size_t)h * NE;
#pragma unroll
        for (int e = 0; e < NE; e++) p[e] = fmaf(xv, g[e], p[e]);
    }
#pragma unroll
    for (int e = 0; e < NE; e++)
#pragma unroll
        for (int o = 16; o > 0; o >>= 1)
            p[e] += __shfl_xor_sync(0xffffffffu, p[e], o);

    __shared__ float s[8][NE];
    int warp = tid >> 5, lane = tid & 31;
    if (lane == 0) {
#pragma unroll
        for (int e = 0; e < NE; e++) s[warp][e] = p[e];
    }
    __syncthreads();
    if (tid == 0) {
        float logit[NE];
#pragma unroll
        for (int e = 0; e < NE; e++) {
            float v = 0.f;
#pragma unroll
            for (int w = 0; w < 8; w++) v += s[w][e];
            logit[e] = v;
        }
        int i0 = 0;
#pragma unroll
        for (int e = 1; e < NE; e++) if (logit[e] > logit[i0]) i0 = e;
        int i1 = -1;
#pragma unroll
        for (int e = 0; e < NE; e++)
            if (e != i0 && (i1 < 0 || logit[e] > logit[i1])) i1 = e;
        float pr = expf(logit[i1] - logit[i0]);
        float w0 = 1.f / (1.f + pr);
        float w1 = pr / (1.f + pr);
        int p0 = atomicAdd(&g_count[i0], 1);
        g_tok[i0 * MAXPE + p0] = t; g_wt[i0 * MAXPE + p0] = w0;
        int p1 = atomicAdd(&g_count[i1], 1);
        g_tok[i1 * MAXPE + p1] = t; g_wt[i1 * MAXPE + p1] = w1;
    }
}

// ---------------------------------------------------------------------------
// FFN1: for expert e, act = silu(X_e @ Wg) * (X_e @ Wu), fused SwiGLU.
// Block: 128 tokens x 64 act-cols (=128 gu-cols, gate/up interleaved in Bs).
// ---------------------------------------------------------------------------
__global__ __launch_bounds__(256) void ffn1_kernel(const float* __restrict__ x,
                                                   const float* __restrict__ w13) {
    const int e = blockIdx.z;
    const int ne = g_count[e];
    const int row0 = blockIdx.x * BM;
    if (row0 >= ne) return;
    const int c0 = blockIdx.y * 64;    // act-column base

    __shared__ int   s_tok[BM];
    __shared__ float As[BK][BM];
    __shared__ float Bs[BK][128];

    const int tid = threadIdx.x;
    if (tid < BM) {
        int r = row0 + tid;
        s_tok[tid] = (r < ne) ? g_tok[e * MAXPE + r] : -1;
    }
    __syncthreads();

    const int ty = tid >> 4;   // row group 0..15 (8 rows each)
    const int tx = tid & 15;   // col group 0..15 (8 gu-cols each)

    float acc[8][8];
#pragma unroll
    for (int i = 0; i < 8; i++)
#pragma unroll
        for (int j = 0; j < 8; j++) acc[i][j] = 0.f;

    // A-load mapping: 2 threads per row, 2 float4 each
    const int ar  = tid >> 1;
    const int ak4 = (tid & 1) * 2;
    const int atok = s_tok[ar];
    // B-load mapping: even j -> gate col, odd j -> up col (interleaved)
    const int bj  = tid & 127;
    const int bk0 = (tid >> 7) * 8;
    const int bcol = (bj & 1) ? (ID + c0 + (bj >> 1)) : (c0 + (bj >> 1));
    const float* bptr = w13 + (size_t)e * HD * (2 * ID) + bcol;

    for (int k0 = 0; k0 < HD; k0 += BK) {
        float4 a0 = make_float4(0.f, 0.f, 0.f, 0.f), a1 = a0;
        if (atok >= 0) {
            const float4* src = (const float4*)(x + (size_t)atok * HD + k0);
            a0 = src[ak4]; a1 = src[ak4 + 1];
        }
        float breg[8];
#pragma unroll
        for (int kk = 0; kk < 8; kk++)
            breg[kk] = bptr[(size_t)(k0 + bk0 + kk) * (2 * ID)];
        __syncthreads();
        As[ak4 * 4 + 0][ar] = a0.x; As[ak4 * 4 + 1][ar] = a0.y;
        As[ak4 * 4 + 2][ar] = a0.z; As[ak4 * 4 + 3][ar] = a0.w;
        As[ak4 * 4 + 4][ar] = a1.x; As[ak4 * 4 + 5][ar] = a1.y;
        As[ak4 * 4 + 6][ar] = a1.z; As[ak4 * 4 + 7][ar] = a1.w;
#pragma unroll
        for (int kk = 0; kk < 8; kk++) Bs[bk0 + kk][bj] = breg[kk];
        __syncthreads();
#pragma unroll
        for (int k = 0; k < BK; k++) {
            float4 av0 = *(const float4*)&As[k][ty * 8];
            float4 av1 = *(const float4*)&As[k][ty * 8 + 4];
            float4 bv0 = *(const float4*)&Bs[k][tx * 8];
            float4 bv1 = *(const float4*)&Bs[k][tx * 8 + 4];
            float a[8] = {av0.x, av0.y, av0.z, av0.w, av1.x, av1.y, av1.z, av1.w};
            float b[8] = {bv0.x, bv0.y, bv0.z, bv0.w, bv1.x, bv1.y, bv1.z, bv1.w};
#pragma unroll
            for (int i = 0; i < 8; i++)
#pragma unroll
                for (int j = 0; j < 8; j++)
                    acc[i][j] = fmaf(a[i], b[j], acc[i][j]);
        }
    }

    // SwiGLU epilogue: acc[i][2p] = gate, acc[i][2p+1] = up
#pragma unroll
    for (int i = 0; i < 8; i++) {
        int r = row0 + ty * 8 + i;
        if (r < ne) {
            float4 v;
            float* vp = &v.x;
#pragma unroll
            for (int p = 0; p < 4; p++) {
                float g = acc[i][2 * p];
                float u = acc[i][2 * p + 1];
                float sg = g / (1.f + __expf(-g));
                vp[p] = sg * u;
            }
            *(float4*)&g_act[(size_t)(e * MAXPE + r) * ID + c0 + tx * 4] = v;
        }
    }
}

// ---------------------------------------------------------------------------
// FFN2: out[tok] += w * (act_e @ W2_e). Block: 128 slots x 128 out-cols.
// ---------------------------------------------------------------------------
__global__ __launch_bounds__(256) void ffn2_kernel(const float* __restrict__ w2,
                                                   float* __restrict__ out) {
    const int e = blockIdx.z;
    const int ne = g_count[e];
    const int row0 = blockIdx.x * BM;
    if (row0 >= ne) return;
    const int c0 = blockIdx.y * 128;

    __shared__ int   s_tok[BM];
    __shared__ float s_wt[BM];
    __shared__ float As[BK][BM];
    __shared__ float Bs[BK][128];

    const int tid = threadIdx.x;
    if (tid < BM) {
        int r = row0 + tid;
        s_tok[tid] = (r < ne) ? g_tok[e * MAXPE + r] : -1;
        s_wt[tid]  = (r < ne) ? g_wt[e * MAXPE + r] : 0.f;
    }
    __syncthreads();

    const int ty = tid >> 4;
    const int tx = tid & 15;

    float acc[8][8];
#pragma unroll
    for (int i = 0; i < 8; i++)
#pragma unroll
        for (int j = 0; j < 8; j++) acc[i][j] = 0.f;

    const int ar  = tid >> 1;
    const int ak4 = (tid & 1) * 2;
    const bool avalid = (row0 + ar) < ne;
    const float* aptr = g_act + (size_t)(e * MAXPE + row0 + ar) * ID;

    const int bj  = tid & 127;
    const int bk0 = (tid >> 7) * 8;
    const float* bptr = w2 + (size_t)e * ID * HD + c0 + bj;

    for (int k0 = 0; k0 < ID; k0 += BK) {
        float4 a0 = make_float4(0.f, 0.f, 0.f, 0.f), a1 = a0;
        if (avalid) {
            const float4* src = (const float4*)(aptr + k0);
            a0 = src[ak4]; a1 = src[ak4 + 1];
        }
        float breg[8];
#pragma unroll
        for (int kk = 0; kk < 8; kk++)
            breg[kk] = bptr[(size_t)(k0 + bk0 + kk) * HD];
        __syncthreads();
        As[ak4 * 4 + 0][ar] = a0.x; As[ak4 * 4 + 1][ar] = a0.y;
        As[ak4 * 4 + 2][ar] = a0.z; As[ak4 * 4 + 3][ar] = a0.w;
        As[ak4 * 4 + 4][ar] = a1.x; As[ak4 * 4 + 5][ar] = a1.y;
        As[ak4 * 4 + 6][ar] = a1.z; As[ak4 * 4 + 7][ar] = a1.w;
#pragma unroll
        for (int kk = 0; kk < 8; kk++) Bs[bk0 + kk][bj] = breg[kk];
        __syncthreads();
#pragma unroll
        for (int k = 0; k < BK; k++) {
            float4 av0 = *(const float4*)&As[k][ty * 8];
            float4 av1 = *(const float4*)&As[k][ty * 8 + 4];
            float4 bv0 = *(const float4*)&Bs[k][tx * 8];
            float4 bv1 = *(const float4*)&Bs[k][tx * 8 + 4];
            float a[8] = {av0.x, av0.y, av0.z, av0.w, av1.x, av1.y, av1.z, av1.w};
            float b[8] = {bv0.x, bv0.y, bv0.z, bv0.w, bv1.x, bv1.y, bv1.z, bv1.w};
#pragma unroll
            for (int i = 0; i < 8; i++)
#pragma unroll
                for (int j = 0; j < 8; j++)
                    acc[i][j] = fmaf(a[i], b[j], acc[i][j]);
        }
    }

    // weighted scatter-add (each token hits exactly 2 experts; two-value float
    // add is commutative -> deterministic output)
#pragma unroll
    for (int i = 0; i < 8; i++) {
        int rl = ty * 8 + i;
        int tok = s_tok[rl];
        if (tok >= 0) {
            float w = s_wt[rl];
            float* orow = out + (size_t)tok * HD + c0 + tx * 8;
#pragma unroll
            for (int j = 0; j < 8; j++)
                atomicAdd(&orow[j], w * acc[i][j]);
        }
    }
}

// ---------------------------------------------------------------------------
extern "C" void kernel_launch(void* const* d_in, const int* in_sizes, int n_in,
                              void* d_out, int out_size) {
    const float* x   = (const float*)d_in[0];   // hidden_states [T, H]
    const float* gw  = (const float*)d_in[1];   // gate_w        [H, E]
    const float* w13 = (const float*)d_in[2];   // w13           [E, H, 2I]
    const float* w2  = (const float*)d_in[3];   // w2            [E, I, H]
    float* out = (float*)d_out;                 // [T, H] f32

    init_kernel<<<(NTOK * HD / 4 + 255) / 256, 256>>>((float4*)out);
    router_kernel<<<NTOK, 256>>>(x, gw);
    dim3 g1(MAXPE / BM, ID / 64, NE);           // (16, 16, 8)
    ffn1_kernel<<<g1, 256>>>(x, w13);
    dim3 g2(MAXPE / BM, HD / 128, NE);          // (16, 16, 8)
    ffn2_kernel<<<g2, 256>>>(w2, out);
}

// round 2
// speedup vs baseline: 1.0026x; 1.0026x over previous
#include <cuda_runtime.h>
#include <math.h>

// Problem constants
#define NTOK 2048
#define HD   2048
#define NE   8
#define ID   1024
#define MAXPE 2048   // worst case: all tokens pick this expert

// Tiling
#define BM 128
#define BK 16

// Scratch (static device memory; no runtime allocation)
__device__ int   g_count[NE];
__device__ int   g_tok[NE * MAXPE];
__device__ float g_wt [NE * MAXPE];
__device__ float g_act[(size_t)NE * MAXPE * ID];   // 64 MB activation scratch

// ---------------------------------------------------------------------------
// init: zero expert counters and the output buffer (poisoned by harness)
// ---------------------------------------------------------------------------
__global__ void init_kernel(float4* __restrict__ out4) {
    int idx = blockIdx.x * blockDim.x + threadIdx.x;
    if (idx < NE) g_count[idx] = 0;
    if (idx < NTOK * HD / 4) out4[idx] = make_float4(0.f, 0.f, 0.f, 0.f);
}

// ---------------------------------------------------------------------------
// router: logits -> top-2 -> renormalized weights -> per-expert gather lists
// topk(softmax) == topk(logits); renorm(top2 of softmax) == softmax over the
// top-2 logits, so compute it directly.
// ---------------------------------------------------------------------------
__global__ void router_kernel(const float* __restrict__ x,
                              const float* __restrict__ gw) {
    int t = blockIdx.x;
    int tid = threadIdx.x;
    float p[NE];
#pragma unroll
    for (int e = 0; e < NE; e++) p[e] = 0.f;
    const float* xr = x + (size_t)t * HD;
    for (int h = tid; h < HD; h += 256) {
        float xv = xr[h];
        const float* g = gw + (size_t)h * NE;
#pragma unroll
        for (int e = 0; e < NE; e++) p[e] = fmaf(xv, g[e], p[e]);
    }
#pragma unroll
    for (int e = 0; e < NE; e++)
#pragma unroll
        for (int o = 16; o > 0; o >>= 1)
            p[e] += __shfl_xor_sync(0xffffffffu, p[e], o);

    __shared__ float s[8][NE];
    int warp = tid >> 5, lane = tid & 31;
    if (lane == 0) {
#pragma unroll
        for (int e = 0; e < NE; e++) s[warp][e] = p[e];
    }
    __syncthreads();
    if (tid == 0) {
        float logit[NE];
#pragma unroll
        for (int e = 0; e < NE; e++) {
            float v = 0.f;
#pragma unroll
            for (int w = 0; w < 8; w++) v += s[w][e];
            logit[e] = v;
        }
        int i0 = 0;
#pragma unroll
        for (int e = 1; e < NE; e++) if (logit[e] > logit[i0]) i0 = e;
        int i1 = -1;
#pragma unroll
        for (int e = 0; e < NE; e++)
            if (e != i0 && (i1 < 0 || logit[e] > logit[i1])) i1 = e;
        float pr = expf(logit[i1] - logit[i0]);
        float w0 = 1.f / (1.f + pr);
        float w1 = pr / (1.f + pr);
        int p0 = atomicAdd(&g_count[i0], 1);
        g_tok[i0 * MAXPE + p0] = t; g_wt[i0 * MAXPE + p0] = w0;
        int p1 = atomicAdd(&g_count[i1], 1);
        g_tok[i1 * MAXPE + p1] = t; g_wt[i1 * MAXPE + p1] = w1;
    }
}

// ---------------------------------------------------------------------------
// FFN1: for expert e, act = silu(X_e @ Wg) * (X_e @ Wu), fused SwiGLU.
// Block: 128 tokens x 64 act-cols (=128 gu-cols, gate/up interleaved in Bs).
// ---------------------------------------------------------------------------
__global__ __launch_bounds__(256) void ffn1_kernel(const float* __restrict__ x,
                                                   const float* __restrict__ w13) {
    const int e = blockIdx.z;
    const int ne = g_count[e];
    const int row0 = blockIdx.x * BM;
    if (row0 >= ne) return;
    const int c0 = blockIdx.y * 64;    // act-column base

    __shared__ int   s_tok[BM];
    __shared__ float As[BK][BM];
    __shared__ float Bs[BK][128];

    const int tid = threadIdx.x;
    if (tid < BM) {
        int r = row0 + tid;
        s_tok[tid] = (r < ne) ? g_tok[e * MAXPE + r] : -1;
    }
    __syncthreads();

    const int ty = tid >> 4;   // row group 0..15 (8 rows each)
    const int tx = tid & 15;   // col group 0..15 (8 gu-cols each)

    float acc[8][8];
#pragma unroll
    for (int i = 0; i < 8; i++)
#pragma unroll
        for (int j = 0; j < 8; j++) acc[i][j] = 0.f;

    // A-load mapping: 2 threads per row, 2 float4 each
    const int ar  = tid >> 1;
    const int ak4 = (tid & 1) * 2;
    const int atok = s_tok[ar];
    // B-load mapping: even j -> gate col, odd j -> up col (interleaved)
    const int bj  = tid & 127;
    const int bk0 = (tid >> 7) * 8;
    const int bcol = (bj & 1) ? (ID + c0 + (bj >> 1)) : (c0 + (bj >> 1));
    const float* bptr = w13 + (size_t)e * HD * (2 * ID) + bcol;

    for (int k0 = 0; k0 < HD; k0 += BK) {
        float4 a0 = make_float4(0.f, 0.f, 0.f, 0.f), a1 = a0;
        if (atok >= 0) {
            const float4* src = (const float4*)(x + (size_t)atok * HD + k0);
            a0 = src[ak4]; a1 = src[ak4 + 1];
        }
        float breg[8];
#pragma unroll
        for (int kk = 0; kk < 8; kk++)
            breg[kk] = bptr[(size_t)(k0 + bk0 + kk) * (2 * ID)];
        __syncthreads();
        As[ak4 * 4 + 0][ar] = a0.x; As[ak4 * 4 + 1][ar] = a0.y;
        As[ak4 * 4 + 2][ar] = a0.z; As[ak4 * 4 + 3][ar] = a0.w;
        As[ak4 * 4 + 4][ar] = a1.x; As[ak4 * 4 + 5][ar] = a1.y;
        As[ak4 * 4 + 6][ar] = a1.z; As[ak4 * 4 + 7][ar] = a1.w;
#pragma unroll
        for (int kk = 0; kk < 8; kk++) Bs[bk0 + kk][bj] = breg[kk];
        __syncthreads();
#pragma unroll
        for (int k = 0; k < BK; k++) {
            float4 av0 = *(const float4*)&As[k][ty * 8];
            float4 av1 = *(const float4*)&As[k][ty * 8 + 4];
            float4 bv0 = *(const float4*)&Bs[k][tx * 8];
            float4 bv1 = *(const float4*)&Bs[k][tx * 8 + 4];
            float a[8] = {av0.x, av0.y, av0.z, av0.w, av1.x, av1.y, av1.z, av1.w};
            float b[8] = {bv0.x, bv0.y, bv0.z, bv0.w, bv1.x, bv1.y, bv1.z, bv1.w};
#pragma unroll
            for (int i = 0; i < 8; i++)
#pragma unroll
                for (int j = 0; j < 8; j++)
                    acc[i][j] = fmaf(a[i], b[j], acc[i][j]);
        }
    }

    // SwiGLU epilogue: acc[i][2p] = gate, acc[i][2p+1] = up
#pragma unroll
    for (int i = 0; i < 8; i++) {
        int r = row0 + ty * 8 + i;
        if (r < ne) {
            float4 v;
            float* vp = &v.x;
#pragma unroll
            for (int p = 0; p < 4; p++) {
                float g = acc[i][2 * p];
                float u = acc[i][2 * p + 1];
                float sg = g / (1.f + __expf(-g));
                vp[p] = sg * u;
            }
            *(float4*)&g_act[(size_t)(e * MAXPE + r) * ID + c0 + tx * 4] = v;
        }
    }
}

// ---------------------------------------------------------------------------
// FFN2: out[tok] += w * (act_e @ W2_e). Block: 128 slots x 128 out-cols.
// ---------------------------------------------------------------------------
__global__ __launch_bounds__(256) void ffn2_kernel(const float* __restrict__ w2,
                                                   float* __restrict__ out) {
    const int e = blockIdx.z;
    const int ne = g_count[e];
    const int row0 = blockIdx.x * BM;
    if (row0 >= ne) return;
    const int c0 = blockIdx.y * 128;

    __shared__ int   s_tok[BM];
    __shared__ float s_wt[BM];
    __shared__ float As[BK][BM];
    __shared__ float Bs[BK][128];

    const int tid = threadIdx.x;
    if (tid < BM) {
        int r = row0 + tid;
        s_tok[tid] = (r < ne) ? g_tok[e * MAXPE + r] : -1;
        s_wt[tid]  = (r < ne) ? g_wt[e * MAXPE + r] : 0.f;
    }
    __syncthreads();

    const int ty = tid >> 4;
    const int tx = tid & 15;

    float acc[8][8];
#pragma unroll
    for (int i = 0; i < 8; i++)
#pragma unroll
        for (int j = 0; j < 8; j++) acc[i][j] = 0.f;

    const int ar  = tid >> 1;
    const int ak4 = (tid & 1) * 2;
    const bool avalid = (row0 + ar) < ne;
    const float* aptr = g_act + (size_t)(e * MAXPE + row0 + ar) * ID;

    const int bj  = tid & 127;
    const int bk0 = (tid >> 7) * 8;
    const float* bptr = w2 + (size_t)e * ID * HD + c0 + bj;

    for (int k0 = 0; k0 < ID; k0 += BK) {
        float4 a0 = make_float4(0.f, 0.f, 0.f, 0.f), a1 = a0;
        if (avalid) {
            const float4* src = (const float4*)(aptr + k0);
            a0 = src[ak4]; a1 = src[ak4 + 1];
        }
        float breg[8];
#pragma unroll
        for (int kk = 0; kk < 8; kk++)
            breg[kk] = bptr[(size_t)(k0 + bk0 + kk) * HD];
        __syncthreads();
        As[ak4 * 4 + 0][ar] = a0.x; As[ak4 * 4 + 1][ar] = a0.y;
        As[ak4 * 4 + 2][ar] = a0.z; As[ak4 * 4 + 3][ar] = a0.w;
        As[ak4 * 4 + 4][ar] = a1.x; As[ak4 * 4 + 5][ar] = a1.y;
        As[ak4 * 4 + 6][ar] = a1.z; As[ak4 * 4 + 7][ar] = a1.w;
#pragma unroll
        for (int kk = 0; kk < 8; kk++) Bs[bk0 + kk][bj] = breg[kk];
        __syncthreads();
#pragma unroll
        for (int k = 0; k < BK; k++) {
            float4 av0 = *(const float4*)&As[k][ty * 8];
            float4 av1 = *(const float4*)&As[k][ty * 8 + 4];
            float4 bv0 = *(const float4*)&Bs[k][tx * 8];
            float4 bv1 = *(const float4*)&Bs[k][tx * 8 + 4];
            float a[8] = {av0.x, av0.y, av0.z, av0.w, av1.x, av1.y, av1.z, av1.w};
            float b[8] = {bv0.x, bv0.y, bv0.z, bv0.w, bv1.x, bv1.y, bv1.z, bv1.w};
#pragma unroll
            for (int i = 0; i < 8; i++)
#pragma unroll
                for (int j = 0; j < 8; j++)
                    acc[i][j] = fmaf(a[i], b[j], acc[i][j]);
        }
    }

    // weighted scatter-add (each token hits exactly 2 experts; two-value float
    // add is commutative -> deterministic output)
#pragma unroll
    for (int i = 0; i < 8; i++) {
        int rl = ty * 8 + i;
        int tok = s_tok[rl];
        if (tok >= 0) {
            float w = s_wt[rl];
            float* orow = out + (size_t)tok * HD + c0 + tx * 8;
#pragma unroll
            for (int j = 0; j < 8; j++)
                atomicAdd(&orow[j], w * acc[i][j]);
        }
    }
}

// ---------------------------------------------------------------------------
extern "C" void kernel_launch(void* const* d_in, const int* in_sizes, int n_in,
                              void* d_out, int out_size) {
    const float* x   = (const float*)d_in[0];   // hidden_states [T, H]
    const float* gw  = (const float*)d_in[1];   // gate_w        [H, E]
    const float* w13 = (const float*)d_in[2];   // w13           [E, H, 2I]
    const float* w2  = (const float*)d_in[3];   // w2            [E, I, H]
    float* out = (float*)d_out;                 // [T, H] f32

    init_kernel<<<(NTOK * HD / 4 + 255) / 256, 256>>>((float4*)out);
    router_kernel<<<NTOK, 256>>>(x, gw);
    dim3 g1(MAXPE / BM, ID / 64, NE);           // (16, 16, 8)
    ffn1_kernel<<<g1, 256>>>(x, w13);
    dim3 g2(MAXPE / BM, HD / 128, NE);          // (16, 16, 8)
    ffn2_kernel<<<g2, 256>>>(w2, out);
}

// round 5
// speedup vs baseline: 2.3771x; 2.3709x over previous
#include <cuda_runtime.h>
#include <cstdint>
#include <math.h>

#define NTOK 2048
#define HD   2048
#define NE   8
#define ID   1024
#define MAXPE 2048
#define KC   32

__device__ int   g_count[NE];
__device__ int   g_tok[NE * MAXPE];
__device__ float g_wt [NE * MAXPE];
__device__ float g_act[(size_t)NE * MAXPE * ID];

// ---------------- helpers ----------------
__device__ __forceinline__ uint32_t smem_u32(const void* p) {
    uint32_t a;
    asm("{ .reg .u64 t; cvta.to.shared.u64 t, %1; cvt.u32.u64 %0, t; }" : "=r"(a) : "l"(p));
    return a;
}
#define STS128(v0, v1, v2, v3, a) \
    asm volatile("st.shared.v4.b32 [%0], {%1, %2, %3, %4};" :: "r"(a), "r"(v0), "r"(v1), "r"(v2), "r"(v3) : "memory")

__device__ __forceinline__ void cvt_hl(float a0, float a1, uint32_t& hi, uint32_t& lo) {
    uint32_t h;
    asm("cvt.rn.bf16x2.f32 %0, %1, %2;" : "=r"(h) : "f"(a1), "f"(a0));  // lo16=a0, hi16=a1
    float h0 = __uint_as_float(h << 16);
    float h1 = __uint_as_float(h & 0xFFFF0000u);
    uint32_t l;
    float l1 = a1 - h1, l0 = a0 - h0;
    asm("cvt.rn.bf16x2.f32 %0, %1, %2;" : "=r"(l) : "f"(l1), "f"(l0));
    hi = h; lo = l;
}
__device__ __forceinline__ void mma16816(float* c, const uint32_t* a, const uint32_t* b) {
    asm volatile("mma.sync.aligned.m16n8k16.row.col.f32.bf16.bf16.f32 "
        "{%0,%1,%2,%3}, {%4,%5,%6,%7}, {%8,%9}, {%0,%1,%2,%3};"
        : "+f"(c[0]), "+f"(c[1]), "+f"(c[2]), "+f"(c[3])
        : "r"(a[0]), "r"(a[1]), "r"(a[2]), "r"(a[3]), "r"(b[0]), "r"(b[1]));
}
__device__ __forceinline__ void ldsm4(uint32_t* r, uint32_t addr) {
    asm volatile("ldmatrix.sync.aligned.m8n8.x4.shared.b16 {%0,%1,%2,%3}, [%4];"
        : "=r"(r[0]), "=r"(r[1]), "=r"(r[2]), "=r"(r[3]) : "r"(addr));
}
__device__ __forceinline__ void ldsm4t(uint32_t* r, uint32_t addr) {
    asm volatile("ldmatrix.sync.aligned.m8n8.x4.trans.shared.b16 {%0,%1,%2,%3}, [%4];"
        : "=r"(r[0]), "=r"(r[1]), "=r"(r[2]), "=r"(r[3]) : "r"(addr));
}

// SMEM layout (dynamic)
#define ASTRIDE 80            // 128 rows x (64B data + 16B pad)
#define BSTRIDE 272           // 32 k-rows x (256B data + 16B pad)
#define SZ_A (128 * ASTRIDE)  // 10240
#define SZ_B (32 * BSTRIDE)   // 8704
#define OFF_AH 0
#define OFF_AL SZ_A
#define OFF_BH (2 * SZ_A)
#define OFF_BL (2 * SZ_A + SZ_B)
#define STAGE_SZ (2 * SZ_A + 2 * SZ_B)  // 37888
#define SM_TOK 0
#define SM_WT  512
#define SM_STAGE 1024
#define SMEM_SZ (1024 + 2 * STAGE_SZ)   // 76800

// ---------------------------------------------------------------------------
__global__ void init_kernel(float4* __restrict__ out4) {
    int idx = blockIdx.x * blockDim.x + threadIdx.x;
    if (idx < NE) g_count[idx] = 0;
    if (idx < NTOK * HD / 4) out4[idx] = make_float4(0.f, 0.f, 0.f, 0.f);
}

// ---------------------------------------------------------------------------
__global__ void router_kernel(const float* __restrict__ x,
                              const float* __restrict__ gw) {
    int t = blockIdx.x, tid = threadIdx.x;
    float p[NE];
#pragma unroll
    for (int e = 0; e < NE; e++) p[e] = 0.f;
    const float* xr = x + (size_t)t * HD;
    for (int h = tid; h < HD; h += 256) {
        float xv = xr[h];
        const float* g = gw + (size_t)h * NE;
#pragma unroll
        for (int e = 0; e < NE; e++) p[e] = fmaf(xv, g[e], p[e]);
    }
#pragma unroll
    for (int e = 0; e < NE; e++)
#pragma unroll
        for (int o = 16; o > 0; o >>= 1)
            p[e] += __shfl_xor_sync(0xffffffffu, p[e], o);
    __shared__ float s[8][NE];
    int warp = tid >> 5, lane = tid & 31;
    if (lane == 0)
#pragma unroll
        for (int e = 0; e < NE; e++) s[warp][e] = p[e];
    __syncthreads();
    if (tid == 0) {
        float logit[NE];
#pragma unroll
        for (int e = 0; e < NE; e++) {
            float v = 0.f;
#pragma unroll
            for (int w = 0; w < 8; w++) v += s[w][e];
            logit[e] = v;
        }
        int i0 = 0;
#pragma unroll
        for (int e = 1; e < NE; e++) if (logit[e] > logit[i0]) i0 = e;
        int i1 = -1;
#pragma unroll
        for (int e = 0; e < NE; e++)
            if (e != i0 && (i1 < 0 || logit[e] > logit[i1])) i1 = e;
        float pr = expf(logit[i1] - logit[i0]);
        int p0 = atomicAdd(&g_count[i0], 1);
        g_tok[i0 * MAXPE + p0] = t; g_wt[i0 * MAXPE + p0] = 1.f / (1.f + pr);
        int p1 = atomicAdd(&g_count[i1], 1);
        g_tok[i1 * MAXPE + p1] = t; g_wt[i1 * MAXPE + p1] = pr / (1.f + pr);
    }
}

// ---------------------------------------------------------------------------
// GEMM body: double-buffered fp32->bf16(hi/lo) staging + mma.sync, CTA 128x128.
// 8 warps as 4(M) x 2(N): warp tile 32 x 64. 3 MMA passes: ah*bh, al*bh, ah*bl.
// IL=true: pack B word w = (region0[w], region1[w])  (gate/up interleave)
// IL=false: B word w = pair of consecutive floats from concat(r0, r1)
// ---------------------------------------------------------------------------
template <int NCHUNK, bool IL>
__device__ __forceinline__ void gemm_body(
    const float* __restrict__ arow,
    const float* __restrict__ br0, const float* __restrict__ br1,
    int bkstride, uint32_t sb, float c[2][8][4])
{
    const int tid = threadIdx.x;
    const int lane = tid & 31, w = tid >> 5;
    const int wm = w & 3, wn = w >> 2;
    const int s_row = tid >> 1, s_half = tid & 1;   // A staging: 2 thr/row
    const int s_k = tid >> 3, s_seg = tid & 7;      // B staging: 8 thr/k-row

    const int lrow8 = ((lane >> 3) & 1) * 8 + (lane & 7);
    const int lk16 = (lane & 16) ? 16 : 0;
    const uint32_t a_base = (uint32_t)(wm * 32 + lrow8) * ASTRIDE + lk16;
    const uint32_t b_base = (uint32_t)lrow8 * BSTRIDE + wn * 128 + lk16;

    float ar[16], b0r[8], b1r[8];

    auto fetch = [&](int k0) {
        if (arow) {
            const float4* p = (const float4*)(arow + k0 + s_half * 16);
#pragma unroll
            for (int i = 0; i < 4; i++) ((float4*)ar)[i] = p[i];
        } else {
#pragma unroll
            for (int i = 0; i < 16; i++) ar[i] = 0.f;
        }
        const float* p0 = br0 + (size_t)(k0 + s_k) * bkstride;
        const float* p1 = br1 + (size_t)(k0 + s_k) * bkstride;
#pragma unroll
        for (int i = 0; i < 2; i++) {
            ((float4*)b0r)[i] = ((const float4*)p0)[i];
            ((float4*)b1r)[i] = ((const float4*)p1)[i];
        }
    };
    auto stage = [&](int buf) {
        uint32_t st = sb + SM_STAGE + buf * STAGE_SZ;
        uint32_t hi[8], lo[8];
#pragma unroll
        for (int i = 0; i < 8; i++) cvt_hl(ar[2 * i], ar[2 * i + 1], hi[i], lo[i]);
        uint32_t ad = st + OFF_AH + s_row * ASTRIDE + s_half * 32;
        STS128(hi[0], hi[1], hi[2], hi[3], ad);
        STS128(hi[4], hi[5], hi[6], hi[7], ad + 16);
        ad += (OFF_AL - OFF_AH);
        STS128(lo[0], lo[1], lo[2], lo[3], ad);
        STS128(lo[4], lo[5], lo[6], lo[7], ad + 16);
        uint32_t bhi[8], blo[8];
#pragma unroll
        for (int i = 0; i < 8; i++) {
            float fa, fb;
            if (IL)          { fa = b0r[i];        fb = b1r[i]; }
            else if (i < 4)  { fa = b0r[2 * i];    fb = b0r[2 * i + 1]; }
            else             { fa = b1r[2 * i - 8]; fb = b1r[2 * i - 7]; }
            cvt_hl(fa, fb, bhi[i], blo[i]);
        }
        uint32_t bd = st + OFF_BH + s_k * BSTRIDE + s_seg * 32;
        STS128(bhi[0], bhi[1], bhi[2], bhi[3], bd);
        STS128(bhi[4], bhi[5], bhi[6], bhi[7], bd + 16);
        bd += (OFF_BL - OFF_BH);
        STS128(blo[0], blo[1], blo[2], blo[3], bd);
        STS128(blo[4], blo[5], blo[6], blo[7], bd + 16);
    };
    auto compute = [&](int buf) {
        uint32_t st = sb + SM_STAGE + buf * STAGE_SZ;
#pragma unroll
        for (int s = 0; s < 2; s++) {
            uint32_t ah[2][4], al[2][4], bh[8][2];
#pragma unroll
            for (int mt = 0; mt < 2; mt++) {
                uint32_t ao = st + OFF_AH + a_base + mt * 16 * ASTRIDE + s * 32;
                ldsm4(ah[mt], ao);
                ldsm4(al[mt], ao + (OFF_AL - OFF_AH));
            }
#pragma unroll
            for (int jp = 0; jp < 4; jp++) {
                uint32_t r[4];
                ldsm4t(r, st + OFF_BH + b_base + s * 16 * BSTRIDE + jp * 32);
                bh[2 * jp][0] = r[0]; bh[2 * jp][1] = r[1];
                bh[2 * jp + 1][0] = r[2]; bh[2 * jp + 1][1] = r[3];
            }
#pragma unroll
            for (int mt = 0; mt < 2; mt++)
#pragma unroll
                for (int j = 0; j < 8; j++) mma16816(c[mt][j], ah[mt], bh[j]);
#pragma unroll
            for (int mt = 0; mt < 2; mt++)
#pragma unroll
                for (int j = 0; j < 8; j++) mma16816(c[mt][j], al[mt], bh[j]);
#pragma unroll
            for (int jp = 0; jp < 4; jp++) {
                uint32_t r[4];
                ldsm4t(r, st + OFF_BL + b_base + s * 16 * BSTRIDE + jp * 32);
#pragma unroll
                for (int mt = 0; mt < 2; mt++) {
                    mma16816(c[mt][2 * jp], ah[mt], r);
                    mma16816(c[mt][2 * jp + 1], ah[mt], r + 2);
                }
            }
        }
    };

    fetch(0);
    stage(0);
    __syncthreads();
#pragma unroll 1
    for (int ch = 0; ch < NCHUNK; ch++) {
        if (ch + 1 < NCHUNK) fetch((ch + 1) * KC);
        compute(ch & 1);
        if (ch + 1 < NCHUNK) stage((ch + 1) & 1);
        __syncthreads();
    }
}

// ---------------------------------------------------------------------------
// FFN1: act = silu(Xe @ Wg) * (Xe @ Wu). CTA: 128 rows x 64 act cols
// (B n-cols interleaved: even=gate, odd=up -> SiLU pairs in c0/c1 of a thread).
// ---------------------------------------------------------------------------
__global__ void __launch_bounds__(256, 1)
ffn1_mma(const float* __restrict__ x, const float* __restrict__ w13) {
    const int e = blockIdx.z;
    const int ne = g_count[e];
    const int row0 = blockIdx.x * 128;
    if (row0 >= ne) return;
    const int cbase = blockIdx.y * 64;

    extern __shared__ char smem[];
    uint32_t sb = smem_u32(smem);
    const int tid = threadIdx.x;
    if (tid < 128) {
        int r = row0 + tid;
        ((int*)(smem + SM_TOK))[tid] = (r < ne) ? g_tok[e * MAXPE + r] : -1;
    }
    __syncthreads();
    const int mytok = ((const int*)(smem + SM_TOK))[tid >> 1];
    const float* arow = (mytok >= 0) ? (x + (size_t)mytok * HD) : nullptr;
    const int s_seg = tid & 7;
    const float* we = w13 + (size_t)e * HD * (2 * ID);
    const float* br0 = we + cbase + 8 * s_seg;        // gate
    const float* br1 = we + ID + cbase + 8 * s_seg;   // up

    float c[2][8][4];
#pragma unroll
    for (int i = 0; i < 2; i++)
#pragma unroll
        for (int j = 0; j < 8; j++)
#pragma unroll
            for (int k = 0; k < 4; k++) c[i][j][k] = 0.f;

    gemm_body<HD / KC, true>(arow, br0, br1, 2 * ID, sb, c);

    const int lane = tid & 31, w = tid >> 5, wm = w & 3, wn = w >> 2;
    const int g = lane >> 2, t = lane & 3;
#pragma unroll
    for (int mt = 0; mt < 2; mt++)
#pragma unroll
        for (int rr = 0; rr < 2; rr++) {
            int slot = row0 + wm * 32 + mt * 16 + rr * 8 + g;
            if (slot < ne) {
                float* dst = g_act + ((size_t)(e * MAXPE) + slot) * ID + cbase + wn * 32;
#pragma unroll
                for (int j = 0; j < 8; j++) {
                    float gg = c[mt][j][2 * rr], uu = c[mt][j][2 * rr + 1];
                    dst[j * 4 + t] = gg / (1.f + __expf(-gg)) * uu;
                }
            }
        }
}

// ---------------------------------------------------------------------------
// FFN2: out[tok] += wt * (act_e @ W2_e). CTA: 128 rows x 128 out cols.
// ---------------------------------------------------------------------------
__global__ void __launch_bounds__(256, 1)
ffn2_mma(const float* __restrict__ w2, float* __restrict__ out) {
    const int e = blockIdx.z;
    const int ne = g_count[e];
    const int row0 = blockIdx.x * 128;
    if (row0 >= ne) return;
    const int c0 = blockIdx.y * 128;

    extern __shared__ char smem[];
    uint32_t sb = smem_u32(smem);
    const int tid = threadIdx.x;
    if (tid < 128) {
        int r = row0 + tid;
        ((int*)(smem + SM_TOK))[tid]  = (r < ne) ? g_tok[e * MAXPE + r] : -1;
        ((float*)(smem + SM_WT))[tid] = (r < ne) ? g_wt[e * MAXPE + r] : 0.f;
    }
    __syncthreads();
    const int s_row = tid >> 1;
    const bool avalid = (row0 + s_row) < ne;
    const float* arow = avalid ? (g_act + (size_t)(e * MAXPE + row0 + s_row) * ID) : nullptr;
    const int s_seg = tid & 7;
    const float* wb = w2 + (size_t)e * ID * HD + c0 + 16 * s_seg;

    float c[2][8][4];
#pragma unroll
    for (int i = 0; i < 2; i++)
#pragma unroll
        for (int j = 0; j < 8; j++)
#pragma unroll
            for (int k = 0; k < 4; k++) c[i][j][k] = 0.f;

    gemm_body<ID / KC, false>(arow, wb, wb + 8, HD, sb, c);

    const int lane = tid & 31, w = tid >> 5, wm = w & 3, wn = w >> 2;
    const int g = lane >> 2, t = lane & 3;
#pragma unroll
    for (int mt = 0; mt < 2; mt++)
#pragma unroll
        for (int rr = 0; rr < 2; rr++) {
            int rlocal = wm * 32 + mt * 16 + rr * 8 + g;
            int tok = ((const int*)(smem + SM_TOK))[rlocal];
            if (tok >= 0) {
                float wt = ((const float*)(smem + SM_WT))[rlocal];
                float* orow = out + (size_t)tok * HD + c0 + wn * 64;
#pragma unroll
                for (int j = 0; j < 8; j++) {
                    atomicAdd(&orow[j * 8 + 2 * t],     wt * c[mt][j][2 * rr]);
                    atomicAdd(&orow[j * 8 + 2 * t + 1], wt * c[mt][j][2 * rr + 1]);
                }
            }
        }
}

// ---------------------------------------------------------------------------
extern "C" void kernel_launch(void* const* d_in, const int* in_sizes, int n_in,
                              void* d_out, int out_size) {
    const float* x   = (const float*)d_in[0];
    const float* gw  = (const float*)d_in[1];
    const float* w13 = (const float*)d_in[2];
    const float* w2  = (const float*)d_in[3];
    float* out = (float*)d_out;

    cudaFuncSetAttribute(ffn1_mma, cudaFuncAttributeMaxDynamicSharedMemorySize, SMEM_SZ);
    cudaFuncSetAttribute(ffn2_mma, cudaFuncAttributeMaxDynamicSharedMemorySize, SMEM_SZ);

    init_kernel<<<(NTOK * HD / 4 + 255) / 256, 256>>>((float4*)out);
    router_kernel<<<NTOK, 256>>>(x, gw);
    dim3 g1(MAXPE / 128, ID / 64, NE);    // (16, 16, 8)
    ffn1_mma<<<g1, 256, SMEM_SZ>>>(x, w13);
    dim3 g2(MAXPE / 128, HD / 128, NE);   // (16, 16, 8)
    ffn2_mma<<<g2, 256, SMEM_SZ>>>(w2, out);
}